// round 14
// baseline (speedup 1.0000x reference)
#include <cuda_runtime.h>
#include <cuda_fp16.h>
#include <cstdint>

// ---------------------------------------------------------------------------
// Problem constants
// ---------------------------------------------------------------------------
#define D_MODEL 768
#define SEQ     2048
#define NHEADS  12
#define DH      64
#define MROWS   (2 * SEQ)
#define WSZ     (D_MODEL * D_MODEL)

// ---------------------------------------------------------------------------
// Global scratch (allocation-free rule). Pure fp16 operands.
// ---------------------------------------------------------------------------
__device__ __half g_xf[MROWS * D_MODEL];
__device__ __half g_wf[4 * WSZ];
// head-major [h][m][64] fp16
__device__ __half g_qf[NHEADS * MROWS * DH];
__device__ __half g_kf[NHEADS * MROWS * DH];
__device__ __half g_vf[NHEADS * MROWS * DH];
__device__ __half g_atf[MROWS * D_MODEL];
__device__ float g_x[MROWS * D_MODEL];

// ---------------------------------------------------------------------------
// PTX helpers
// ---------------------------------------------------------------------------
__device__ __forceinline__ uint32_t smem_u32(const void* p) {
    uint32_t a;
    asm("{ .reg .u64 t; cvta.to.shared.u64 t, %1; cvt.u32.u64 %0, t; }"
        : "=r"(a) : "l"(p));
    return a;
}

#define MMA_F16(d, a, b) \
    asm volatile("mma.sync.aligned.m16n8k16.row.col.f32.f16.f16.f32 " \
        "{%0,%1,%2,%3}, {%4,%5,%6,%7}, {%8,%9}, {%0,%1,%2,%3};" \
        : "+f"((d)[0]), "+f"((d)[1]), "+f"((d)[2]), "+f"((d)[3]) \
        : "r"((a)[0]), "r"((a)[1]), "r"((a)[2]), "r"((a)[3]), \
          "r"((b)[0]), "r"((b)[1]))

#define LDSM4(r, addr) \
    asm volatile("ldmatrix.sync.aligned.m8n8.x4.shared.b16 {%0,%1,%2,%3}, [%4];" \
        : "=r"((r)[0]), "=r"((r)[1]), "=r"((r)[2]), "=r"((r)[3]) : "r"(addr))

#define LDSM4T(r, addr) \
    asm volatile("ldmatrix.sync.aligned.m8n8.x4.trans.shared.b16 {%0,%1,%2,%3}, [%4];" \
        : "=r"((r)[0]), "=r"((r)[1]), "=r"((r)[2]), "=r"((r)[3]) : "r"(addr))

#define CP16(dst, src) \
    asm volatile("cp.async.cg.shared.global [%0], [%1], 16;" \
                 :: "r"(dst), "l"(src))
#define CP_COMMIT() asm volatile("cp.async.commit_group;" ::: "memory")
#define CP_WAIT(N)  asm volatile("cp.async.wait_group %0;" :: "n"(N) : "memory")

// packed half2 exp2 (sm_75+ PTX, single SFU op for two values)
#define EX2_F16X2(d, a) \
    asm("ex2.approx.f16x2 %0, %1;" : "=r"(d) : "r"(a))

// SW128 swizzle: rows of 128B; conflict-free ldmatrix
#define SW128(off) ((off) ^ (((off) >> 3) & 0x70))

// pack (x,y) as fp16x2
__device__ __forceinline__ uint32_t cvt_f16x2(float x, float y) {
    __half2 h = __floats2half2_rn(x, y);
    return *(uint32_t*)&h;
}

// ---------------------------------------------------------------------------
// One merged split pass: X and the four weights -> fp16 (rounded)
// ---------------------------------------------------------------------------
struct SplitSrcs { const float* p[5]; };

#define NX4 (MROWS * D_MODEL / 4)   // 786432
#define NW4 (WSZ / 4)               // 147456

__global__ void split_all(SplitSrcs s,
                          __half* __restrict__ xf, __half* __restrict__ wf)
{
    const int total = NX4 + 4 * NW4;
    for (int i = blockIdx.x * blockDim.x + threadIdx.x; i < total;
         i += gridDim.x * blockDim.x) {
        int seg, off;
        if (i < NX4) { seg = 0; off = i; }
        else { const int j = i - NX4; seg = 1 + j / NW4; off = j - (seg - 1) * NW4; }
        const float4 v = ((const float4*)s.p[seg])[off];
        uint32_t* dst = (seg == 0) ? (uint32_t*)xf
                                   : (uint32_t*)(wf + (size_t)(seg - 1) * WSZ);
        dst[2 * off]     = cvt_f16x2(v.x, v.y);
        dst[2 * off + 1] = cvt_f16x2(v.z, v.w);
    }
}

// ---------------------------------------------------------------------------
// GEMM: fp16 x fp16 -> fp32 acc, single MMA.
// CTA tile 128 x 64, BK=64 (128B rows, SW128), 3-stage cp.async ring
// (1 sync/iter), 12 k-iters, 8 warps, 3 CTAs/SM.
// MODE 0: O-proj -> fp32 C = acc + bias + R
// MODE 1: QKV -> head-major fp16; z picks W/bias/out
// ---------------------------------------------------------------------------
#define G_ATIL 16384
#define NTILE  64
#define B_TIL  (NTILE * 128)
#define G_STAGE (G_ATIL + B_TIL)        // 24576
#define G_SMEM  (3 * G_STAGE)           // 73728

struct GemmAux {
    const float* bias[3];
    __half* oh[3];
    const float* R;
    float* C;
};

template <int MODE>
__global__ __launch_bounds__(256, 3) void gemm_bs(
    const __half* __restrict__ Ah, const __half* __restrict__ WfB, GemmAux aux)
{
    constexpr int WN = NTILE / 2;      // 32 per-warp N
    constexpr int NT = WN / 8;         // 4 n-frags per warp
    constexpr int NCHUNK = (128 + NTILE) * 8;  // 1536 16B chunks per stage
    constexpr int PERTHR = NCHUNK / 256;       // 6

    extern __shared__ char sm[];
    const uint32_t sb = smem_u32(sm);
    const int tid = threadIdx.x;
    const int lane = tid & 31;
    const int warp = tid >> 5;
    const int wm = warp >> 1;
    const int wn = warp & 1;
    const int bm = blockIdx.y * 128;
    const int bn = blockIdx.x * NTILE;
    const int z = (MODE == 1) ? blockIdx.z : 0;

    const __half* Bf = WfB + (size_t)z * WSZ;
    const float* bias = aux.bias[z];

    auto load_stage = [&](int kt, int st) {
        const uint32_t dst0 = sb + st * G_STAGE;
#pragma unroll
        for (int i = 0; i < PERTHR; i++) {
            const int c = tid + i * 256;
            int r, toff;
            const __half* base;
            if (c < 1024) {                      // A: 1024 chunks
                r = c >> 3; toff = 0; base = Ah;
            } else {
                const int j = c - 1024;
                r = j >> 3; toff = G_ATIL; base = Bf;
            }
            const int ch = c & 7;
            const int grow = ((c < 1024) ? bm : bn) + r;
            const char* src = (const char*)(base + (size_t)grow * D_MODEL + kt * 64)
                            + ch * 16;
            const uint32_t off = SW128((uint32_t)r * 128 + (uint32_t)ch * 16);
            CP16(dst0 + toff + off, src);
        }
        CP_COMMIT();
    };

    load_stage(0, 0);
    load_stage(1, 1);
    CP_WAIT(1);
    __syncthreads();

    float acc[2][NT][4];
#pragma unroll
    for (int mt = 0; mt < 2; mt++)
#pragma unroll
        for (int nt = 0; nt < NT; nt++)
#pragma unroll
            for (int c = 0; c < 4; c++) acc[mt][nt][c] = 0.f;

    int cur = 0, isl = 2;
    for (int kt = 0; kt < 12; kt++) {
        if (kt < 10) {
            load_stage(kt + 2, isl);
            isl = (isl == 2) ? 0 : isl + 1;
        }
        const uint32_t sA = sb + cur * G_STAGE;
        cur = (cur == 2) ? 0 : cur + 1;

#pragma unroll
        for (int ks = 0; ks < 4; ks++) {
            uint32_t ah[2][4];
#pragma unroll
            for (int mt = 0; mt < 2; mt++) {
                const int r = wm * 32 + mt * 16 + (lane & 15);
                const uint32_t off = SW128((uint32_t)r * 128
                                    + (uint32_t)(ks * 2 + (lane >> 4)) * 16);
                LDSM4(ah[mt], sA + off);
            }
            uint32_t bh[4][2];
            {
                const int g = lane >> 3;
                const int rb = wn * WN + (lane & 7) + ((g & 2) ? 8 : 0);
                const int cc = ks * 2 + (g & 1);
#pragma unroll
                for (int np = 0; np < 2; np++) {
                    const int r = rb + np * 16;
                    const uint32_t off = SW128((uint32_t)r * 128 + (uint32_t)cc * 16);
                    LDSM4(&bh[np * 2][0], sA + G_ATIL + off);
                }
            }
#pragma unroll
            for (int mt = 0; mt < 2; mt++)
#pragma unroll
                for (int n4 = 0; n4 < 4; n4++)
                    MMA_F16(acc[mt][n4], ah[mt], bh[n4]);
        }
        if (kt < 10) { CP_WAIT(1); } else { CP_WAIT(0); }
        __syncthreads();
    }

    // epilogue (Q scale folds 1/sqrt(dh) and log2e for exp2 softmax)
    const float scale = (MODE == 1 && z == 0) ? 0.125f * 1.44269504089f : 1.0f;
#pragma unroll
    for (int mt = 0; mt < 2; mt++)
#pragma unroll
        for (int hh = 0; hh < 2; hh++) {
            const int m = bm + wm * 32 + mt * 16 + (lane >> 2) + hh * 8;
#pragma unroll
            for (int nt = 0; nt < NT; nt++) {
                const int col = bn + wn * WN + nt * 8 + (lane & 3) * 2;
                float x0 = acc[mt][nt][2 * hh]     + bias[col];
                float x1 = acc[mt][nt][2 * hh + 1] + bias[col + 1];
                if (MODE == 0) {
                    const float2 rr = *(const float2*)(aux.R + (size_t)m * D_MODEL + col);
                    float2 v = {x0 + rr.x, x1 + rr.y};
                    *(float2*)(aux.C + (size_t)m * D_MODEL + col) = v;
                } else {
                    const int hd = col >> 6;
                    const int dh = col & 63;
                    const size_t oi = ((size_t)hd * MROWS + m) * 32 + (dh >> 1);
                    ((uint32_t*)aux.oh[z])[oi] = cvt_f16x2(x0 * scale, x1 * scale);
                }
            }
        }
}

// ---------------------------------------------------------------------------
// Flash attention: fp16 operands; Q pre-scaled by log2e/8; softmax uses
// packed ex2.approx.f16x2 (P produced directly as fp16x2 MMA fragments).
// CTA = 128 threads (4 warps), 64 q rows. KV tiles of 128 keys, 2-stage
// ring, 16 iters. smem: Q 8192 + 2 x 32768 = 73728 B ; 3 CTAs/SM.
// ---------------------------------------------------------------------------
#define AQ_TIL 8192
#define AKV0   8192
#define AKV_T  16384
#define AKV_S  32768
#define A_SMEM (AKV0 + 2 * AKV_S)   // 73728

__global__ __launch_bounds__(128, 3) void attn_bs(
    const __half* __restrict__ qf_g, const __half* __restrict__ kf_g,
    const __half* __restrict__ vf_g, __half* __restrict__ atf)
{
    extern __shared__ char sm[];
    const uint32_t sb = smem_u32(sm);
    const int tid = threadIdx.x;
    const int lane = tid & 31;
    const int w = tid >> 5;
    const int qb = blockIdx.x * 64;
    const int h = blockIdx.y;
    const int b = blockIdx.z;
    const size_t hq = (size_t)h * MROWS + (size_t)b * SEQ;

    const __half* kvsrc[2] = {kf_g, vf_g};

    // Q loads (join first commit group): 64 rows x 8 chunks = 512
    {
#pragma unroll
        for (int i = 0; i < 4; i++) {
            const int c = tid + i * 128;
            const int r = c >> 3;
            const int ch = c & 7;
            const char* src = (const char*)(qf_g + (hq + qb + r) * DH) + ch * 16;
            const uint32_t off = SW128((uint32_t)r * 128 + (uint32_t)ch * 16);
            CP16(sb + off, src);
        }
    }

    // KV tile of 128 keys: 2 tiles x 128 rows x 8 chunks = 2048 -> 16/thread
    auto load_kv = [&](int it, int st) {
        const int kv = it * 128;
        const uint32_t dst0 = sb + AKV0 + st * AKV_S;
#pragma unroll
        for (int i = 0; i < 16; i++) {
            const int c = tid + i * 128;
            const int t = c >> 10;
            const int r = (c >> 3) & 127;
            const int ch = c & 7;
            const char* src = (const char*)(kvsrc[t] + (hq + kv + r) * DH) + ch * 16;
            const uint32_t off = SW128((uint32_t)r * 128 + (uint32_t)ch * 16);
            CP16(dst0 + t * AKV_T + off, src);
        }
        CP_COMMIT();
    };

    load_kv(0, 0);       // group 0 = Q + kv0
    load_kv(1, 1);       // group 1 = kv1
    CP_WAIT(1);          // Q + kv0 ready
    __syncthreads();

    // hoist Q fragments (reused all 16 iterations)
    uint32_t qf[4][4];
#pragma unroll
    for (int ks = 0; ks < 4; ks++) {
        const int r = w * 16 + (lane & 15);
        const uint32_t off = SW128((uint32_t)r * 128
                            + (uint32_t)(ks * 2 + (lane >> 4)) * 16);
        LDSM4(qf[ks], sb + off);
    }

    float o[8][4];
    float m_run[2] = {-1e30f, -1e30f}, l_run[2] = {0.f, 0.f};
#pragma unroll
    for (int nt = 0; nt < 8; nt++)
#pragma unroll
        for (int c = 0; c < 4; c++) o[nt][c] = 0.f;

    for (int it = 0; it < 16; it++) {
        const uint32_t sK = sb + AKV0 + (it & 1) * AKV_S;
        const uint32_t sV = sK + AKV_T;

        // ---- S = Q K^T  (16 q x 128 keys) ----
        float s[16][4];
#pragma unroll
        for (int nt = 0; nt < 16; nt++)
#pragma unroll
            for (int c = 0; c < 4; c++) s[nt][c] = 0.f;

#pragma unroll
        for (int ks = 0; ks < 4; ks++) {
            uint32_t kh_[16][2];
            const int g = lane >> 3;
            const int nr = (lane & 7) + ((g & 2) ? 8 : 0);
            const int cc = ks * 2 + (g & 1);
#pragma unroll
            for (int np = 0; np < 8; np++) {
                const int r = nr + np * 16;
                const uint32_t off = SW128((uint32_t)r * 128 + (uint32_t)cc * 16);
                LDSM4(&kh_[np * 2][0], sK + off);
            }
#pragma unroll
            for (int nt = 0; nt < 16; nt++)
                MMA_F16(s[nt], qf[ks], kh_[nt]);
        }

        // ---- warp-private online softmax (base-2, packed fp16 exp) ----
        float corr[2];
#pragma unroll
        for (int hh = 0; hh < 2; hh++) {
            float m = -1e30f;
#pragma unroll
            for (int nt = 0; nt < 16; nt++)
                m = fmaxf(m, fmaxf(s[nt][2 * hh], s[nt][2 * hh + 1]));
            m = fmaxf(m, __shfl_xor_sync(0xffffffffu, m, 1));
            m = fmaxf(m, __shfl_xor_sync(0xffffffffu, m, 2));
            const float mn = fmaxf(m_run[hh], m);
            corr[hh] = exp2f(m_run[hh] - mn);
            m_run[hh] = mn;
        }
        // p = exp2(s - m) computed as packed fp16x2, stored back into s bits:
        // s[nt][0] <- P(keys pair, hh=0), s[nt][1] <- P(pair, hh=1)
        float ps[2] = {0.f, 0.f};
#pragma unroll
        for (int nt = 0; nt < 16; nt++) {
            uint32_t e0 = cvt_f16x2(s[nt][0] - m_run[0], s[nt][1] - m_run[0]);
            uint32_t e1 = cvt_f16x2(s[nt][2] - m_run[1], s[nt][3] - m_run[1]);
            uint32_t p0, p1;
            EX2_F16X2(p0, e0);
            EX2_F16X2(p1, e1);
            const float2 f0 = __half22float2(*(__half2*)&p0);
            const float2 f1 = __half22float2(*(__half2*)&p1);
            ps[0] += f0.x + f0.y;
            ps[1] += f1.x + f1.y;
            s[nt][0] = __uint_as_float(p0);
            s[nt][1] = __uint_as_float(p1);
        }
#pragma unroll
        for (int hh = 0; hh < 2; hh++) {
            float v = ps[hh];
            v += __shfl_xor_sync(0xffffffffu, v, 1);
            v += __shfl_xor_sync(0xffffffffu, v, 2);
            l_run[hh] = l_run[hh] * corr[hh] + v;
        }
#pragma unroll
        for (int nt = 0; nt < 8; nt++)
#pragma unroll
            for (int c = 0; c < 4; c++) o[nt][c] *= corr[c >> 1];

        // ---- O += P V (P already packed fp16, ldmatrix.trans V) ----
#pragma unroll
        for (int kc = 0; kc < 8; kc++) {
            uint32_t ph[4];
            ph[0] = __float_as_uint(s[2 * kc][0]);
            ph[1] = __float_as_uint(s[2 * kc][1]);
            ph[2] = __float_as_uint(s[2 * kc + 1][0]);
            ph[3] = __float_as_uint(s[2 * kc + 1][1]);
            uint32_t vh_[8][2];
            const int g = lane >> 3;
            const int kr = kc * 16 + (lane & 7) + ((g & 1) ? 8 : 0);
            const int nf = (g & 2) ? 8 : 0;
#pragma unroll
            for (int np = 0; np < 4; np++) {
                const int cc = np * 2 + (nf >> 3);
                const uint32_t off = SW128((uint32_t)kr * 128 + (uint32_t)cc * 16);
                LDSM4T(&vh_[np * 2][0], sV + off);
            }
#pragma unroll
            for (int nt = 0; nt < 8; nt++)
                MMA_F16(o[nt], ph, vh_[nt]);
        }

        __syncthreads();                 // done reading this stage
        if (it < 14) {
            load_kv(it + 2, it & 1);     // refill freed stage
            CP_WAIT(1);
        } else {
            CP_WAIT(0);
        }
        __syncthreads();
    }

    // ---- epilogue: att as fp16, row-major [M][768] ----
#pragma unroll
    for (int hh = 0; hh < 2; hh++) {
        const float inv = 1.f / l_run[hh];
        const size_t m = (size_t)b * SEQ + qb + w * 16 + (lane >> 2) + hh * 8;
#pragma unroll
        for (int nt = 0; nt < 8; nt++) {
            const int col = h * 64 + nt * 8 + (lane & 3) * 2;
            const size_t oi = (m * D_MODEL + col) >> 1;
            ((uint32_t*)atf)[oi] =
                cvt_f16x2(o[nt][2 * hh] * inv, o[nt][2 * hh + 1] * inv);
        }
    }
}

// ---------------------------------------------------------------------------
// LayerNorm over last dim (768)
// ---------------------------------------------------------------------------
__global__ __launch_bounds__(256) void ln_kernel(
    const float* __restrict__ x, const float* __restrict__ gamma,
    const float* __restrict__ beta, float* __restrict__ out)
{
    const int row = blockIdx.x;
    const float* xr = x + (size_t)row * D_MODEL;
    const int tid = threadIdx.x;

    float v[3];
    float s = 0.f, s2 = 0.f;
#pragma unroll
    for (int i = 0; i < 3; i++) {
        v[i] = xr[tid + i * 256];
        s += v[i];
        s2 += v[i] * v[i];
    }
#pragma unroll
    for (int off = 16; off; off >>= 1) {
        s  += __shfl_xor_sync(0xffffffffu, s,  off);
        s2 += __shfl_xor_sync(0xffffffffu, s2, off);
    }
    __shared__ float rs[8], rs2[8];
    __shared__ float mu_s, rstd_s;
    const int w = tid >> 5;
    if ((tid & 31) == 0) { rs[w] = s; rs2[w] = s2; }
    __syncthreads();
    if (tid == 0) {
        float a = 0.f, bq = 0.f;
#pragma unroll
        for (int i = 0; i < 8; i++) { a += rs[i]; bq += rs2[i]; }
        float mu = a * (1.f / D_MODEL);
        float var = bq * (1.f / D_MODEL) - mu * mu;
        mu_s = mu;
        rstd_s = rsqrtf(var + 1e-5f);
    }
    __syncthreads();
    const float mu = mu_s, rstd = rstd_s;
#pragma unroll
    for (int i = 0; i < 3; i++) {
        int c = tid + i * 256;
        out[(size_t)row * D_MODEL + c] = (v[i] - mu) * rstd * gamma[c] + beta[c];
    }
}

// ---------------------------------------------------------------------------
// kernel_launch — inputs: Q, W_q, b_q, W_k, b_k, W_v, b_v, W_o, b_o,
//                         ln_gamma, ln_beta
// ---------------------------------------------------------------------------
extern "C" void kernel_launch(void* const* d_in, const int* in_sizes, int n_in,
                              void* d_out, int out_size)
{
    const float* X     = (const float*)d_in[0];
    const float* Wq    = (const float*)d_in[1];
    const float* bq    = (const float*)d_in[2];
    const float* Wk    = (const float*)d_in[3];
    const float* bk    = (const float*)d_in[4];
    const float* Wv    = (const float*)d_in[5];
    const float* bv    = (const float*)d_in[6];
    const float* Wo    = (const float*)d_in[7];
    const float* bo    = (const float*)d_in[8];
    const float* gamma = (const float*)d_in[9];
    const float* beta  = (const float*)d_in[10];
    float* out = (float*)d_out;

    const int M = in_sizes[0] / D_MODEL;   // 4096
    const int B = M / SEQ;                 // 2

    __half *xf, *wf, *qf, *kf, *vf, *atf;
    float* x;
    cudaGetSymbolAddress((void**)&xf, g_xf);
    cudaGetSymbolAddress((void**)&wf, g_wf);
    cudaGetSymbolAddress((void**)&qf, g_qf);
    cudaGetSymbolAddress((void**)&kf, g_kf);
    cudaGetSymbolAddress((void**)&vf, g_vf);
    cudaGetSymbolAddress((void**)&atf, g_atf);
    cudaGetSymbolAddress((void**)&x, g_x);

    cudaFuncSetAttribute((const void*)gemm_bs<1>,
                         cudaFuncAttributeMaxDynamicSharedMemorySize, G_SMEM);
    cudaFuncSetAttribute((const void*)gemm_bs<0>,
                         cudaFuncAttributeMaxDynamicSharedMemorySize, G_SMEM);
    cudaFuncSetAttribute((const void*)attn_bs,
                         cudaFuncAttributeMaxDynamicSharedMemorySize, A_SMEM);

    // 1) one merged split pass (fp16 round)
    SplitSrcs ss;
    ss.p[0] = X; ss.p[1] = Wq; ss.p[2] = Wk; ss.p[3] = Wv; ss.p[4] = Wo;
    split_all<<<1184, 256>>>(ss, xf, wf);

    // 2) merged QKV projection (z = 0,1,2) -> head-major fp16 (3 CTAs/SM)
    {
        GemmAux aux;
        aux.bias[0] = bq; aux.bias[1] = bk; aux.bias[2] = bv;
        aux.oh[0] = qf; aux.oh[1] = kf; aux.oh[2] = vf;
        aux.R = nullptr; aux.C = nullptr;
        gemm_bs<1><<<dim3(D_MODEL / NTILE, M / 128, 3), 256, G_SMEM>>>(
            xf, wf, aux);
    }

    // 3) attention -> att fp16
    attn_bs<<<dim3(SEQ / 64, NHEADS, B), 128, A_SMEM>>>(qf, kf, vf, atf);

    // 4) O-projection + residual -> fp32 x (128x64 tiles, 3 CTAs/SM)
    {
        GemmAux aux;
        aux.bias[0] = bo; aux.bias[1] = bo; aux.bias[2] = bo;
        aux.oh[0] = aux.oh[1] = aux.oh[2] = nullptr;
        aux.R = X; aux.C = x;
        gemm_bs<0><<<dim3(D_MODEL / NTILE, M / 128, 1), 256, G_SMEM>>>(
            atf, wf + 3 * (size_t)WSZ, aux);
    }

    // 5) LayerNorm
    ln_kernel<<<M, 256>>>(x, gamma, beta, out);
}

// round 15
// speedup vs baseline: 1.0125x; 1.0125x over previous
#include <cuda_runtime.h>
#include <cuda_fp16.h>
#include <cstdint>

// ---------------------------------------------------------------------------
// Problem constants
// ---------------------------------------------------------------------------
#define D_MODEL 768
#define SEQ     2048
#define NHEADS  12
#define DH      64
#define MROWS   (2 * SEQ)
#define WSZ     (D_MODEL * D_MODEL)

// ---------------------------------------------------------------------------
// Global scratch (allocation-free rule). Pure fp16 operands.
// ---------------------------------------------------------------------------
__device__ __half g_xf[MROWS * D_MODEL];
__device__ __half g_wf[4 * WSZ];
// head-major [h][m][64] fp16
__device__ __half g_qf[NHEADS * MROWS * DH];
__device__ __half g_kf[NHEADS * MROWS * DH];
__device__ __half g_vf[NHEADS * MROWS * DH];
__device__ __half g_atf[MROWS * D_MODEL];
__device__ float g_x[MROWS * D_MODEL];

// ---------------------------------------------------------------------------
// PTX helpers
// ---------------------------------------------------------------------------
__device__ __forceinline__ uint32_t smem_u32(const void* p) {
    uint32_t a;
    asm("{ .reg .u64 t; cvta.to.shared.u64 t, %1; cvt.u32.u64 %0, t; }"
        : "=r"(a) : "l"(p));
    return a;
}

#define MMA_F16(d, a, b) \
    asm volatile("mma.sync.aligned.m16n8k16.row.col.f32.f16.f16.f32 " \
        "{%0,%1,%2,%3}, {%4,%5,%6,%7}, {%8,%9}, {%0,%1,%2,%3};" \
        : "+f"((d)[0]), "+f"((d)[1]), "+f"((d)[2]), "+f"((d)[3]) \
        : "r"((a)[0]), "r"((a)[1]), "r"((a)[2]), "r"((a)[3]), \
          "r"((b)[0]), "r"((b)[1]))

#define LDSM4(r, addr) \
    asm volatile("ldmatrix.sync.aligned.m8n8.x4.shared.b16 {%0,%1,%2,%3}, [%4];" \
        : "=r"((r)[0]), "=r"((r)[1]), "=r"((r)[2]), "=r"((r)[3]) : "r"(addr))

#define LDSM4T(r, addr) \
    asm volatile("ldmatrix.sync.aligned.m8n8.x4.trans.shared.b16 {%0,%1,%2,%3}, [%4];" \
        : "=r"((r)[0]), "=r"((r)[1]), "=r"((r)[2]), "=r"((r)[3]) : "r"(addr))

#define CP16(dst, src) \
    asm volatile("cp.async.cg.shared.global [%0], [%1], 16;" \
                 :: "r"(dst), "l"(src))
#define CP_COMMIT() asm volatile("cp.async.commit_group;" ::: "memory")
#define CP_WAIT(N)  asm volatile("cp.async.wait_group %0;" :: "n"(N) : "memory")

// packed half2 exp2 (single SFU op for two values)
#define EX2_F16X2(d, a) \
    asm("ex2.approx.f16x2 %0, %1;" : "=r"(d) : "r"(a))

// SW128 swizzle: rows of 128B; conflict-free ldmatrix
#define SW128(off) ((off) ^ (((off) >> 3) & 0x70))

// pack (x,y) as fp16x2
__device__ __forceinline__ uint32_t cvt_f16x2(float x, float y) {
    __half2 h = __floats2half2_rn(x, y);
    return *(uint32_t*)&h;
}

// ---------------------------------------------------------------------------
// One merged split pass: X and the four weights -> fp16 (rounded)
// ---------------------------------------------------------------------------
struct SplitSrcs { const float* p[5]; };

#define NX4 (MROWS * D_MODEL / 4)   // 786432
#define NW4 (WSZ / 4)               // 147456

__global__ void split_all(SplitSrcs s,
                          __half* __restrict__ xf, __half* __restrict__ wf)
{
    const int total = NX4 + 4 * NW4;
    for (int i = blockIdx.x * blockDim.x + threadIdx.x; i < total;
         i += gridDim.x * blockDim.x) {
        int seg, off;
        if (i < NX4) { seg = 0; off = i; }
        else { const int j = i - NX4; seg = 1 + j / NW4; off = j - (seg - 1) * NW4; }
        const float4 v = ((const float4*)s.p[seg])[off];
        uint32_t* dst = (seg == 0) ? (uint32_t*)xf
                                   : (uint32_t*)(wf + (size_t)(seg - 1) * WSZ);
        dst[2 * off]     = cvt_f16x2(v.x, v.y);
        dst[2 * off + 1] = cvt_f16x2(v.z, v.w);
    }
}

// ---------------------------------------------------------------------------
// GEMM: fp16 x fp16 -> fp32 acc, single MMA.
// CTA tile 128 x NTILE, BK=64 (128B rows, SW128), 3-stage cp.async ring
// (1 sync/iter), 12 k-iters, 8 warps.
// MODE 0 (NTILE=64, 3 CTAs/SM): O-proj -> fp32 C = acc + bias + R
// MODE 1 (NTILE=128, 2 CTAs/SM): QKV -> head-major fp16; z picks W/bias/out
// ---------------------------------------------------------------------------
#define G_ATIL 16384

struct GemmAux {
    const float* bias[3];
    __half* oh[3];
    const float* R;
    float* C;
};

template <int MODE, int NTILE, int OCC>
__global__ __launch_bounds__(256, OCC) void gemm_bs(
    const __half* __restrict__ Ah, const __half* __restrict__ WfB, GemmAux aux)
{
    constexpr int B_TIL = NTILE * 128;
    constexpr int STAGE = G_ATIL + B_TIL;
    constexpr int WN = NTILE / 2;      // per-warp N
    constexpr int NT = WN / 8;         // n-frags per warp
    constexpr int NCHUNK = (128 + NTILE) * 8;  // 16B chunks per stage
    constexpr int PERTHR = NCHUNK / 256;

    extern __shared__ char sm[];
    const uint32_t sb = smem_u32(sm);
    const int tid = threadIdx.x;
    const int lane = tid & 31;
    const int warp = tid >> 5;
    const int wm = warp >> 1;
    const int wn = warp & 1;
    const int bm = blockIdx.y * 128;
    const int bn = blockIdx.x * NTILE;
    const int z = (MODE == 1) ? blockIdx.z : 0;

    const __half* Bf = WfB + (size_t)z * WSZ;
    const float* bias = aux.bias[z];

    auto load_stage = [&](int kt, int st) {
        const uint32_t dst0 = sb + st * STAGE;
#pragma unroll
        for (int i = 0; i < PERTHR; i++) {
            const int c = tid + i * 256;
            int r, toff;
            const __half* base;
            if (c < 1024) {                      // A: 1024 chunks
                r = c >> 3; toff = 0; base = Ah;
            } else {
                const int j = c - 1024;
                r = j >> 3; toff = G_ATIL; base = Bf;
            }
            const int ch = c & 7;
            const int grow = ((c < 1024) ? bm : bn) + r;
            const char* src = (const char*)(base + (size_t)grow * D_MODEL + kt * 64)
                            + ch * 16;
            const uint32_t off = SW128((uint32_t)r * 128 + (uint32_t)ch * 16);
            CP16(dst0 + toff + off, src);
        }
        CP_COMMIT();
    };

    load_stage(0, 0);
    load_stage(1, 1);
    CP_WAIT(1);
    __syncthreads();

    float acc[2][NT][4];
#pragma unroll
    for (int mt = 0; mt < 2; mt++)
#pragma unroll
        for (int nt = 0; nt < NT; nt++)
#pragma unroll
            for (int c = 0; c < 4; c++) acc[mt][nt][c] = 0.f;

    int cur = 0, isl = 2;
    for (int kt = 0; kt < 12; kt++) {
        if (kt < 10) {
            load_stage(kt + 2, isl);
            isl = (isl == 2) ? 0 : isl + 1;
        }
        const uint32_t sA = sb + cur * STAGE;
        cur = (cur == 2) ? 0 : cur + 1;

#pragma unroll
        for (int ks = 0; ks < 4; ks++) {
            uint32_t ah[2][4];
#pragma unroll
            for (int mt = 0; mt < 2; mt++) {
                const int r = wm * 32 + mt * 16 + (lane & 15);
                const uint32_t off = SW128((uint32_t)r * 128
                                    + (uint32_t)(ks * 2 + (lane >> 4)) * 16);
                LDSM4(ah[mt], sA + off);
            }
#pragma unroll
            for (int qg = 0; qg < NT / 4; qg++) {
                uint32_t bh[4][2];
                const int g = lane >> 3;
                const int rb = wn * WN + qg * 32 + (lane & 7) + ((g & 2) ? 8 : 0);
                const int cc = ks * 2 + (g & 1);
#pragma unroll
                for (int np = 0; np < 2; np++) {
                    const int r = rb + np * 16;
                    const uint32_t off = SW128((uint32_t)r * 128 + (uint32_t)cc * 16);
                    LDSM4(&bh[np * 2][0], sA + G_ATIL + off);
                }
#pragma unroll
                for (int mt = 0; mt < 2; mt++)
#pragma unroll
                    for (int n4 = 0; n4 < 4; n4++)
                        MMA_F16(acc[mt][qg * 4 + n4], ah[mt], bh[n4]);
            }
        }
        if (kt < 10) { CP_WAIT(1); } else { CP_WAIT(0); }
        __syncthreads();
    }

    // epilogue (Q scale folds 1/sqrt(dh) and log2e for exp2 softmax)
    const float scale = (MODE == 1 && z == 0) ? 0.125f * 1.44269504089f : 1.0f;
#pragma unroll
    for (int mt = 0; mt < 2; mt++)
#pragma unroll
        for (int hh = 0; hh < 2; hh++) {
            const int m = bm + wm * 32 + mt * 16 + (lane >> 2) + hh * 8;
#pragma unroll
            for (int nt = 0; nt < NT; nt++) {
                const int col = bn + wn * WN + nt * 8 + (lane & 3) * 2;
                float x0 = acc[mt][nt][2 * hh]     + bias[col];
                float x1 = acc[mt][nt][2 * hh + 1] + bias[col + 1];
                if (MODE == 0) {
                    const float2 rr = *(const float2*)(aux.R + (size_t)m * D_MODEL + col);
                    float2 v = {x0 + rr.x, x1 + rr.y};
                    *(float2*)(aux.C + (size_t)m * D_MODEL + col) = v;
                } else {
                    const int hd = col >> 6;
                    const int dh = col & 63;
                    const size_t oi = ((size_t)hd * MROWS + m) * 32 + (dh >> 1);
                    ((uint32_t*)aux.oh[z])[oi] = cvt_f16x2(x0 * scale, x1 * scale);
                }
            }
        }
}

// ---------------------------------------------------------------------------
// Flash attention: fp16 operands; Q pre-scaled by log2e/8; softmax uses
// packed ex2.approx.f16x2 (P produced directly as fp16x2 MMA fragments).
// CTA = 128 threads (4 warps), 64 q rows. KV tiles of 128 keys, 2-stage
// ring, 16 iters. smem: Q 8192 + 2 x 32768 = 73728 B ; 3 CTAs/SM.
// ---------------------------------------------------------------------------
#define AQ_TIL 8192
#define AKV0   8192
#define AKV_T  16384
#define AKV_S  32768
#define A_SMEM (AKV0 + 2 * AKV_S)   // 73728

__global__ __launch_bounds__(128, 3) void attn_bs(
    const __half* __restrict__ qf_g, const __half* __restrict__ kf_g,
    const __half* __restrict__ vf_g, __half* __restrict__ atf)
{
    extern __shared__ char sm[];
    const uint32_t sb = smem_u32(sm);
    const int tid = threadIdx.x;
    const int lane = tid & 31;
    const int w = tid >> 5;
    const int qb = blockIdx.x * 64;
    const int h = blockIdx.y;
    const int b = blockIdx.z;
    const size_t hq = (size_t)h * MROWS + (size_t)b * SEQ;

    const __half* kvsrc[2] = {kf_g, vf_g};

    // Q loads (join first commit group): 64 rows x 8 chunks = 512
    {
#pragma unroll
        for (int i = 0; i < 4; i++) {
            const int c = tid + i * 128;
            const int r = c >> 3;
            const int ch = c & 7;
            const char* src = (const char*)(qf_g + (hq + qb + r) * DH) + ch * 16;
            const uint32_t off = SW128((uint32_t)r * 128 + (uint32_t)ch * 16);
            CP16(sb + off, src);
        }
    }

    // KV tile of 128 keys: 2 tiles x 128 rows x 8 chunks = 2048 -> 16/thread
    auto load_kv = [&](int it, int st) {
        const int kv = it * 128;
        const uint32_t dst0 = sb + AKV0 + st * AKV_S;
#pragma unroll
        for (int i = 0; i < 16; i++) {
            const int c = tid + i * 128;
            const int t = c >> 10;
            const int r = (c >> 3) & 127;
            const int ch = c & 7;
            const char* src = (const char*)(kvsrc[t] + (hq + kv + r) * DH) + ch * 16;
            const uint32_t off = SW128((uint32_t)r * 128 + (uint32_t)ch * 16);
            CP16(dst0 + t * AKV_T + off, src);
        }
        CP_COMMIT();
    };

    load_kv(0, 0);       // group 0 = Q + kv0
    load_kv(1, 1);       // group 1 = kv1
    CP_WAIT(1);          // Q + kv0 ready
    __syncthreads();

    // hoist Q fragments (reused all 16 iterations)
    uint32_t qf[4][4];
#pragma unroll
    for (int ks = 0; ks < 4; ks++) {
        const int r = w * 16 + (lane & 15);
        const uint32_t off = SW128((uint32_t)r * 128
                            + (uint32_t)(ks * 2 + (lane >> 4)) * 16);
        LDSM4(qf[ks], sb + off);
    }

    float o[8][4];
    float m_run[2] = {-1e30f, -1e30f}, l_run[2] = {0.f, 0.f};
#pragma unroll
    for (int nt = 0; nt < 8; nt++)
#pragma unroll
        for (int c = 0; c < 4; c++) o[nt][c] = 0.f;

    for (int it = 0; it < 16; it++) {
        const uint32_t sK = sb + AKV0 + (it & 1) * AKV_S;
        const uint32_t sV = sK + AKV_T;

        // ---- S = Q K^T  (16 q x 128 keys) ----
        float s[16][4];
#pragma unroll
        for (int nt = 0; nt < 16; nt++)
#pragma unroll
            for (int c = 0; c < 4; c++) s[nt][c] = 0.f;

#pragma unroll
        for (int ks = 0; ks < 4; ks++) {
            uint32_t kh_[16][2];
            const int g = lane >> 3;
            const int nr = (lane & 7) + ((g & 2) ? 8 : 0);
            const int cc = ks * 2 + (g & 1);
#pragma unroll
            for (int np = 0; np < 8; np++) {
                const int r = nr + np * 16;
                const uint32_t off = SW128((uint32_t)r * 128 + (uint32_t)cc * 16);
                LDSM4(&kh_[np * 2][0], sK + off);
            }
#pragma unroll
            for (int nt = 0; nt < 16; nt++)
                MMA_F16(s[nt], qf[ks], kh_[nt]);
        }

        // ---- warp-private online softmax (base-2, packed fp16 exp) ----
        float corr[2];
#pragma unroll
        for (int hh = 0; hh < 2; hh++) {
            float m = -1e30f;
#pragma unroll
            for (int nt = 0; nt < 16; nt++)
                m = fmaxf(m, fmaxf(s[nt][2 * hh], s[nt][2 * hh + 1]));
            m = fmaxf(m, __shfl_xor_sync(0xffffffffu, m, 1));
            m = fmaxf(m, __shfl_xor_sync(0xffffffffu, m, 2));
            const float mn = fmaxf(m_run[hh], m);
            corr[hh] = exp2f(m_run[hh] - mn);
            m_run[hh] = mn;
        }
        // p = exp2(s - m) as packed fp16x2, stored back into s bits:
        // s[nt][0] <- P(c0,c1)  (rows lane>>2),  s[nt][1] <- P(c2,c3) (rows +8)
        float ps[2] = {0.f, 0.f};
#pragma unroll
        for (int nt = 0; nt < 16; nt++) {
            uint32_t e0 = cvt_f16x2(s[nt][0] - m_run[0], s[nt][1] - m_run[0]);
            uint32_t e1 = cvt_f16x2(s[nt][2] - m_run[1], s[nt][3] - m_run[1]);
            uint32_t p0, p1;
            EX2_F16X2(p0, e0);
            EX2_F16X2(p1, e1);
            const float2 f0 = __half22float2(*(__half2*)&p0);
            const float2 f1 = __half22float2(*(__half2*)&p1);
            ps[0] += f0.x + f0.y;
            ps[1] += f1.x + f1.y;
            s[nt][0] = __uint_as_float(p0);
            s[nt][1] = __uint_as_float(p1);
        }
#pragma unroll
        for (int hh = 0; hh < 2; hh++) {
            float v = ps[hh];
            v += __shfl_xor_sync(0xffffffffu, v, 1);
            v += __shfl_xor_sync(0xffffffffu, v, 2);
            l_run[hh] = l_run[hh] * corr[hh] + v;
        }
#pragma unroll
        for (int nt = 0; nt < 8; nt++)
#pragma unroll
            for (int c = 0; c < 4; c++) o[nt][c] *= corr[c >> 1];

        // ---- O += P V (P packed fp16 in s bits, ldmatrix.trans V) ----
#pragma unroll
        for (int kc = 0; kc < 8; kc++) {
            uint32_t ph[4];
            ph[0] = __float_as_uint(s[2 * kc][0]);
            ph[1] = __float_as_uint(s[2 * kc][1]);
            ph[2] = __float_as_uint(s[2 * kc + 1][0]);
            ph[3] = __float_as_uint(s[2 * kc + 1][1]);
            uint32_t vh_[8][2];
            const int g = lane >> 3;
            const int kr = kc * 16 + (lane & 7) + ((g & 1) ? 8 : 0);
            const int nf = (g & 2) ? 8 : 0;
#pragma unroll
            for (int np = 0; np < 4; np++) {
                const int cc = np * 2 + (nf >> 3);
                const uint32_t off = SW128((uint32_t)kr * 128 + (uint32_t)cc * 16);
                LDSM4T(&vh_[np * 2][0], sV + off);
            }
#pragma unroll
            for (int nt = 0; nt < 8; nt++)
                MMA_F16(o[nt], ph, vh_[nt]);
        }

        __syncthreads();                 // done reading this stage
        if (it < 14) {
            load_kv(it + 2, it & 1);     // refill freed stage
            CP_WAIT(1);
        } else {
            CP_WAIT(0);
        }
        __syncthreads();
    }

    // ---- epilogue: att as fp16, row-major [M][768] ----
#pragma unroll
    for (int hh = 0; hh < 2; hh++) {
        const float inv = 1.f / l_run[hh];
        const size_t m = (size_t)b * SEQ + qb + w * 16 + (lane >> 2) + hh * 8;
#pragma unroll
        for (int nt = 0; nt < 8; nt++) {
            const int col = h * 64 + nt * 8 + (lane & 3) * 2;
            const size_t oi = (m * D_MODEL + col) >> 1;
            ((uint32_t*)atf)[oi] =
                cvt_f16x2(o[nt][2 * hh] * inv, o[nt][2 * hh + 1] * inv);
        }
    }
}

// ---------------------------------------------------------------------------
// LayerNorm over last dim (768)
// ---------------------------------------------------------------------------
__global__ __launch_bounds__(256) void ln_kernel(
    const float* __restrict__ x, const float* __restrict__ gamma,
    const float* __restrict__ beta, float* __restrict__ out)
{
    const int row = blockIdx.x;
    const float* xr = x + (size_t)row * D_MODEL;
    const int tid = threadIdx.x;

    float v[3];
    float s = 0.f, s2 = 0.f;
#pragma unroll
    for (int i = 0; i < 3; i++) {
        v[i] = xr[tid + i * 256];
        s += v[i];
        s2 += v[i] * v[i];
    }
#pragma unroll
    for (int off = 16; off; off >>= 1) {
        s  += __shfl_xor_sync(0xffffffffu, s,  off);
        s2 += __shfl_xor_sync(0xffffffffu, s2, off);
    }
    __shared__ float rs[8], rs2[8];
    __shared__ float mu_s, rstd_s;
    const int w = tid >> 5;
    if ((tid & 31) == 0) { rs[w] = s; rs2[w] = s2; }
    __syncthreads();
    if (tid == 0) {
        float a = 0.f, bq = 0.f;
#pragma unroll
        for (int i = 0; i < 8; i++) { a += rs[i]; bq += rs2[i]; }
        float mu = a * (1.f / D_MODEL);
        float var = bq * (1.f / D_MODEL) - mu * mu;
        mu_s = mu;
        rstd_s = rsqrtf(var + 1e-5f);
    }
    __syncthreads();
    const float mu = mu_s, rstd = rstd_s;
#pragma unroll
    for (int i = 0; i < 3; i++) {
        int c = tid + i * 256;
        out[(size_t)row * D_MODEL + c] = (v[i] - mu) * rstd * gamma[c] + beta[c];
    }
}

// ---------------------------------------------------------------------------
// kernel_launch — inputs: Q, W_q, b_q, W_k, b_k, W_v, b_v, W_o, b_o,
//                         ln_gamma, ln_beta
// ---------------------------------------------------------------------------
extern "C" void kernel_launch(void* const* d_in, const int* in_sizes, int n_in,
                              void* d_out, int out_size)
{
    const float* X     = (const float*)d_in[0];
    const float* Wq    = (const float*)d_in[1];
    const float* bq    = (const float*)d_in[2];
    const float* Wk    = (const float*)d_in[3];
    const float* bk    = (const float*)d_in[4];
    const float* Wv    = (const float*)d_in[5];
    const float* bv    = (const float*)d_in[6];
    const float* Wo    = (const float*)d_in[7];
    const float* bo    = (const float*)d_in[8];
    const float* gamma = (const float*)d_in[9];
    const float* beta  = (const float*)d_in[10];
    float* out = (float*)d_out;

    const int M = in_sizes[0] / D_MODEL;   // 4096
    const int B = M / SEQ;                 // 2

    __half *xf, *wf, *qf, *kf, *vf, *atf;
    float* x;
    cudaGetSymbolAddress((void**)&xf, g_xf);
    cudaGetSymbolAddress((void**)&wf, g_wf);
    cudaGetSymbolAddress((void**)&qf, g_qf);
    cudaGetSymbolAddress((void**)&kf, g_kf);
    cudaGetSymbolAddress((void**)&vf, g_vf);
    cudaGetSymbolAddress((void**)&atf, g_atf);
    cudaGetSymbolAddress((void**)&x, g_x);

    constexpr int G_SMEM_128 = 3 * (G_ATIL + 128 * 128);  // 98304
    constexpr int G_SMEM_64  = 3 * (G_ATIL + 64 * 128);   // 73728

    cudaFuncSetAttribute((const void*)gemm_bs<1, 128, 2>,
                         cudaFuncAttributeMaxDynamicSharedMemorySize, G_SMEM_128);
    cudaFuncSetAttribute((const void*)gemm_bs<0, 64, 3>,
                         cudaFuncAttributeMaxDynamicSharedMemorySize, G_SMEM_64);
    cudaFuncSetAttribute((const void*)attn_bs,
                         cudaFuncAttributeMaxDynamicSharedMemorySize, A_SMEM);

    // 1) one merged split pass (fp16 round)
    SplitSrcs ss;
    ss.p[0] = X; ss.p[1] = Wq; ss.p[2] = Wk; ss.p[3] = Wv; ss.p[4] = Wo;
    split_all<<<1184, 256>>>(ss, xf, wf);

    // 2) merged QKV projection (z = 0,1,2) -> head-major fp16 (2 CTAs/SM,
    //    NTILE=128: minimal A re-reads)
    {
        GemmAux aux;
        aux.bias[0] = bq; aux.bias[1] = bk; aux.bias[2] = bv;
        aux.oh[0] = qf; aux.oh[1] = kf; aux.oh[2] = vf;
        aux.R = nullptr; aux.C = nullptr;
        gemm_bs<1, 128, 2><<<dim3(D_MODEL / 128, M / 128, 3), 256, G_SMEM_128>>>(
            xf, wf, aux);
    }

    // 3) attention -> att fp16
    attn_bs<<<dim3(SEQ / 64, NHEADS, B), 128, A_SMEM>>>(qf, kf, vf, atf);

    // 4) O-projection + residual -> fp32 x (128x64 tiles, 3 CTAs/SM)
    {
        GemmAux aux;
        aux.bias[0] = bo; aux.bias[1] = bo; aux.bias[2] = bo;
        aux.oh[0] = aux.oh[1] = aux.oh[2] = nullptr;
        aux.R = X; aux.C = x;
        gemm_bs<0, 64, 3><<<dim3(D_MODEL / 64, M / 128, 1), 256, G_SMEM_64>>>(
            atf, wf + 3 * (size_t)WSZ, aux);
    }

    // 5) LayerNorm
    ln_kernel<<<M, 256>>>(x, gamma, beta, out);
}